// round 8
// baseline (speedup 1.0000x reference)
#include <cuda_runtime.h>
#include <cuda_fp16.h>
#include <math.h>
#include <stdint.h>

#define NN 8192
#define DD 256
#define CAP 2048

// ================= scratch (device globals) =================================
__device__ float  g_H0[NN * DD];            // x @ W (pre-relu, pre-agg)
__device__ float  g_ACC[NN * DD];           // segment-sum accumulator
__device__ float  g_Wt[DD * DD];            // W transposed
__device__ __half g_Hh[NN * DD];            // fp16 hi part of h
__device__ __half g_Hl[NN * DD];            // fp16 lo part (h - hi)
__device__ float  g_SQ[NN];                 // row squared norms of h
__device__ float  g_DIST[(size_t)NN * NN];  // pairwise distances (256 MB)
__device__ float  g_S[NN];                  // per-row distance threshold
__device__ float  g_DF[NN];                 // diagonal membership flag

// ================= PTX helpers ==============================================
__device__ __forceinline__ uint32_t smem_u32(const void* p) {
    uint32_t a;
    asm("{ .reg .u64 t; cvta.to.shared.u64 t, %1; cvt.u32.u64 %0, t; }"
        : "=r"(a) : "l"(p));
    return a;
}
__device__ __forceinline__ void cpa16(uint32_t dst, const void* src) {
    asm volatile("cp.async.cg.shared.global [%0], [%1], 16;"
                 :: "r"(dst), "l"(src) : "memory");
}
#define CPA_COMMIT() asm volatile("cp.async.commit_group;" ::: "memory")
#define CPA_WAIT(n)  asm volatile("cp.async.wait_group %0;" :: "n"(n) : "memory")

#define LDSM4(r0, r1, r2, r3, addr)                                           \
    asm volatile("ldmatrix.sync.aligned.m8n8.x4.shared.b16 {%0,%1,%2,%3}, [%4];" \
                 : "=r"(r0), "=r"(r1), "=r"(r2), "=r"(r3) : "r"(addr))

// D += A(16x16 f16) * B(16x8 f16)^T, fp32 accum
#define MMA16816(c, a, b)                                                     \
    asm volatile("mma.sync.aligned.m16n8k16.row.col.f32.f16.f16.f32 "         \
                 "{%0,%1,%2,%3}, {%4,%5,%6,%7}, {%8,%9}, {%0,%1,%2,%3};"      \
                 : "+f"((c)[0]), "+f"((c)[1]), "+f"((c)[2]), "+f"((c)[3])     \
                 : "r"((a)[0]), "r"((a)[1]), "r"((a)[2]), "r"((a)[3]),        \
                   "r"((b)[0]), "r"((b)[1]))

// ================= reductions ===============================================
__device__ __forceinline__ float blockSum(float v, float* red) {
    int lane = threadIdx.x & 31, wid = threadIdx.x >> 5;
#pragma unroll
    for (int o = 16; o; o >>= 1) v += __shfl_xor_sync(0xffffffffu, v, o);
    if (lane == 0) red[wid] = v;
    __syncthreads();
    if (threadIdx.x < 32) {
        float x = (lane < 8) ? red[lane] : 0.f;
#pragma unroll
        for (int o = 4; o; o >>= 1) x += __shfl_xor_sync(0xffffffffu, x, o);
        if (lane == 0) red[0] = x;
    }
    __syncthreads();
    float r = red[0];
    __syncthreads();
    return r;
}
__device__ __forceinline__ float blockMin(float v, float* red) {
    int lane = threadIdx.x & 31, wid = threadIdx.x >> 5;
#pragma unroll
    for (int o = 16; o; o >>= 1) v = fminf(v, __shfl_xor_sync(0xffffffffu, v, o));
    if (lane == 0) red[wid] = v;
    __syncthreads();
    if (threadIdx.x < 32) {
        float x = (lane < 8) ? red[lane] : 3.4e38f;
#pragma unroll
        for (int o = 4; o; o >>= 1) x = fminf(x, __shfl_xor_sync(0xffffffffu, x, o));
        if (lane == 0) red[0] = x;
    }
    __syncthreads();
    float r = red[0];
    __syncthreads();
    return r;
}

// ================= small kernels ============================================
__global__ void transpose_w(const float* __restrict__ W, float* __restrict__ Wt) {
    int idx = blockIdx.x * 256 + threadIdx.x;
    int n = idx >> 8, k = idx & 255;
    Wt[idx] = W[k * DD + n];
}

__global__ void __launch_bounds__(256)
scatter_edges(const float* __restrict__ H0, const int* __restrict__ edges, int nE,
              float* __restrict__ ACC) {
    int gid = blockIdx.x * 256 + threadIdx.x;
    int e = gid >> 6;
    if (e >= nE) return;
    int c = (gid & 63) << 2;
    int sN = edges[e];
    int dN = edges[nE + e];
    const float4 v = *(const float4*)(H0 + (size_t)sN * DD + c);
    float* p = ACC + (size_t)dN * DD + c;
    asm volatile("red.global.add.v4.f32 [%0], {%1,%2,%3,%4};"
                 :: "l"(p), "f"(v.x), "f"(v.y), "f"(v.z), "f"(v.w) : "memory");
}

// h = relu(H0+ACC) -> Hout; SQ = |h|^2; fp16 split -> Hh, Hl
__global__ void __launch_bounds__(256)
relu_split(const float* __restrict__ H0, const float* __restrict__ ACC,
           float* __restrict__ Hout, float* __restrict__ SQ,
           __half* __restrict__ Hh, __half* __restrict__ Hl) {
    __shared__ float red[8];
    int r = blockIdx.x, c = threadIdx.x;
    size_t i = (size_t)r * DD + c;
    float v = fmaxf(H0[i] + ACC[i], 0.f);
    Hout[i] = v;
    __half hh = __float2half_rn(v);
    float lo = v - __half2float(hh);
    Hh[i] = hh;
    Hl[i] = __float2half_rn(lo);
    float ss = blockSum(v * v, red);
    if (c == 0) SQ[r] = ss;
}

// ================= SIMT NT SGEMM for H0 = x @ W (f32x2) =====================
__device__ __forceinline__ unsigned long long dup2(float x) {
    unsigned long long r;
    asm("mov.b64 %0, {%1,%1};" : "=l"(r) : "f"(x));
    return r;
}
__device__ __forceinline__ void ffma2(unsigned long long& d, unsigned long long a,
                                      unsigned long long b) {
    asm("fma.rn.f32x2 %0, %1, %2, %0;" : "+l"(d) : "l"(a), "l"(b));
}
__device__ __forceinline__ float2 unpack2(unsigned long long v) {
    float2 r;
    asm("mov.b64 {%0,%1}, %2;" : "=f"(r.x), "=f"(r.y) : "l"(v));
    return r;
}

__global__ void __launch_bounds__(256)
gemm_h0(const float* __restrict__ A, const float* __restrict__ B,
        float* __restrict__ C, int N, int K) {
    __shared__ float As[8][132];
    __shared__ float Bs[8][132];
    const int bi = blockIdx.y * 128;
    const int bj = blockIdx.x * 128;
    const int t = threadIdx.x;
    const int tx = t & 15, ty = t >> 4;
    const int lr = t >> 1, lc = (t & 1) * 4;

    unsigned long long acc2[8][4];
#pragma unroll
    for (int i = 0; i < 8; i++)
#pragma unroll
        for (int j = 0; j < 4; j++) acc2[i][j] = 0ull;

    const float* Ag = A + (size_t)(bi + lr) * K + lc;
    const float* Bg = B + (size_t)(bj + lr) * K + lc;
    float4 av = *(const float4*)Ag;
    float4 bv = *(const float4*)Bg;

    for (int k0 = 0; k0 < K; k0 += 8) {
        As[lc + 0][lr] = av.x; As[lc + 1][lr] = av.y;
        As[lc + 2][lr] = av.z; As[lc + 3][lr] = av.w;
        Bs[lc + 0][lr] = bv.x; Bs[lc + 1][lr] = bv.y;
        Bs[lc + 2][lr] = bv.z; Bs[lc + 3][lr] = bv.w;
        __syncthreads();
        if (k0 + 8 < K) {
            av = *(const float4*)(Ag + k0 + 8);
            bv = *(const float4*)(Bg + k0 + 8);
        }
#pragma unroll
        for (int kk = 0; kk < 8; kk++) {
            float ar[8];
            *(float4*)(ar)     = *(const float4*)(&As[kk][ty * 8]);
            *(float4*)(ar + 4) = *(const float4*)(&As[kk][ty * 8 + 4]);
            const unsigned long long* bp = (const unsigned long long*)(&Bs[kk][tx * 8]);
            unsigned long long b0 = bp[0], b1 = bp[1], b2 = bp[2], b3 = bp[3];
#pragma unroll
            for (int i = 0; i < 8; i++) {
                unsigned long long ai = dup2(ar[i]);
                ffma2(acc2[i][0], ai, b0);
                ffma2(acc2[i][1], ai, b1);
                ffma2(acc2[i][2], ai, b2);
                ffma2(acc2[i][3], ai, b3);
            }
        }
        __syncthreads();
    }
#pragma unroll
    for (int i = 0; i < 8; i++) {
        size_t row = (size_t)(bi + ty * 8 + i) * N + bj + tx * 8;
        float2 v0 = unpack2(acc2[i][0]), v1 = unpack2(acc2[i][1]);
        float2 v2 = unpack2(acc2[i][2]), v3 = unpack2(acc2[i][3]);
        *(float4*)(C + row)     = make_float4(v0.x, v0.y, v1.x, v1.y);
        *(float4*)(C + row + 4) = make_float4(v2.x, v2.y, v3.x, v3.y);
    }
}

// ================= fp16x3 mma.sync dist GEMM (triangular) ===================
// CTA tile 128x128, K=256 in 16 chunks of 16, double-buffered cp.async.
// dot = Hh*Hh^T + Hh*Hl^T + Hl*Hh^T; epi: dist = sqrt(sq_i+sq_j-2dot),
// stored normal + mirrored (dist is symmetric).
//
// SMEM (bytes): [0,512) sq_i  [512,1024) sq_j  [1024,+) slabs / fp32 stage
// slab buffer b at 1024 + b*24576: Ahi +0, Alo +6144, Bhi +12288, Blo +18432
// each slab: 128 rows x 16 halfs, row stride 48B (24 halfs; 16B-aligned and
// ldmatrix bank-conflict-free).
#define SLAB_STRIDE 48
#define BUF_BYTES 24576
#define DIST_SMEM (1024 + 128 * 132 * 4)   // 68608 (>= 1024 + 2*24576)

static __device__ __forceinline__ void load_chunk(
    int t, uint32_t slabBase, int c, int bi, int bj,
    const __half* __restrict__ Hh, const __half* __restrict__ Hl) {
    int row = t >> 1, half = t & 1;
    uint32_t dst = slabBase + (uint32_t)(row * SLAB_STRIDE + half * 16);
    size_t ko = (size_t)c * 16 + half * 8;
    cpa16(dst,         Hh + (size_t)(bi + row) * DD + ko);
    cpa16(dst + 6144,  Hl + (size_t)(bi + row) * DD + ko);
    cpa16(dst + 12288, Hh + (size_t)(bj + row) * DD + ko);
    cpa16(dst + 18432, Hl + (size_t)(bj + row) * DD + ko);
}

__global__ void __launch_bounds__(256)
dist_mma(const __half* __restrict__ Hh, const __half* __restrict__ Hl,
         const float* __restrict__ SQ, float* __restrict__ DIST) {
    extern __shared__ char dyn[];
    const uint32_t sb = smem_u32(dyn);
    const int t = threadIdx.x;
    const int w = t >> 5, lane = t & 31;

    // triangular tile mapping: blockIdx.x -> (i, j), j <= i
    int L = blockIdx.x;
    int i = (int)((sqrtf(8.f * (float)L + 1.f) - 1.f) * 0.5f);
    while ((i + 1) * (i + 2) / 2 <= L) i++;
    while (i * (i + 1) / 2 > L) i--;
    int j = L - i * (i + 1) / 2;
    const int bi = i * 128;
    const int bj = j * 128;
    const bool diag = (bi == bj);

    // sq caches
    if (t < 128) ((float*)dyn)[t] = SQ[bi + t];
    else         ((float*)dyn)[t] = SQ[bj + t - 128];

    const int mOff = (w >> 2) * 64;     // 2 warp-rows of 64
    const int nOff = (w & 3) * 32;      // 4 warp-cols of 32

    float acc[4][4][4];
#pragma unroll
    for (int a = 0; a < 4; a++)
#pragma unroll
        for (int b = 0; b < 4; b++)
#pragma unroll
            for (int c = 0; c < 4; c++) acc[a][b][c] = 0.f;

    load_chunk(t, sb + 1024, 0, bi, bj, Hh, Hl);
    CPA_COMMIT();

    // ldmatrix base addresses (per-lane)
    const uint32_t aHiBase = sb + 1024 + (uint32_t)((mOff + (lane & 15)) * SLAB_STRIDE
                                                    + (lane >> 4) * 16);
    const uint32_t bHiBase = sb + 1024 + 12288 +
        (uint32_t)((nOff + ((lane >> 4) * 8) + (lane & 7)) * SLAB_STRIDE
                   + ((lane >> 3) & 1) * 16);

    for (int s = 0; s < 16; s++) {
        uint32_t bufOff = (uint32_t)(s & 1) * BUF_BYTES;
        if (s < 15) {
            load_chunk(t, sb + 1024 + (uint32_t)((s + 1) & 1) * BUF_BYTES,
                       s + 1, bi, bj, Hh, Hl);
            CPA_COMMIT();
            CPA_WAIT(1);
        } else {
            CPA_WAIT(0);
        }
        __syncthreads();

        uint32_t ahi[4][4], alo[4][4], bhi[4][2], blo[4][2];
#pragma unroll
        for (int mi = 0; mi < 4; mi++) {
            uint32_t ad = aHiBase + bufOff + mi * 16 * SLAB_STRIDE;
            LDSM4(ahi[mi][0], ahi[mi][1], ahi[mi][2], ahi[mi][3], ad);
            LDSM4(alo[mi][0], alo[mi][1], alo[mi][2], alo[mi][3], ad + 6144);
        }
#pragma unroll
        for (int p = 0; p < 2; p++) {
            uint32_t bd = bHiBase + bufOff + p * 16 * SLAB_STRIDE;
            uint32_t r0, r1, r2, r3;
            LDSM4(r0, r1, r2, r3, bd);
            bhi[2 * p][0] = r0; bhi[2 * p][1] = r1;
            bhi[2 * p + 1][0] = r2; bhi[2 * p + 1][1] = r3;
            LDSM4(r0, r1, r2, r3, bd + 6144);
            blo[2 * p][0] = r0; blo[2 * p][1] = r1;
            blo[2 * p + 1][0] = r2; blo[2 * p + 1][1] = r3;
        }
#pragma unroll
        for (int mi = 0; mi < 4; mi++)
#pragma unroll
            for (int ni = 0; ni < 4; ni++) {
                MMA16816(acc[mi][ni], ahi[mi], bhi[ni]);
                MMA16816(acc[mi][ni], ahi[mi], blo[ni]);
                MMA16816(acc[mi][ni], alo[mi], bhi[ni]);
            }
        __syncthreads();
    }

    // ---- epilogue: dist = sqrt(max(sq_i + sq_j - 2*dot, 0)) ----------------
    const float* sqi = (const float*)dyn;
    const float* sqj = (const float*)dyn + 128;
    float* stage = (float*)(dyn + 1024);        // [128][132]
    const int g = lane >> 2, tc2 = (lane & 3) * 2;

#pragma unroll
    for (int mi = 0; mi < 4; mi++) {
        int r0 = mOff + mi * 16 + g;
        float si0 = sqi[r0], si1 = sqi[r0 + 8];
#pragma unroll
        for (int ni = 0; ni < 4; ni++) {
            int c0 = nOff + ni * 8 + tc2;
            float sj0 = sqj[c0], sj1 = sqj[c0 + 1];
            float d00 = sqrtf(fmaxf(si0 + sj0 - 2.f * acc[mi][ni][0], 0.f));
            float d01 = sqrtf(fmaxf(si0 + sj1 - 2.f * acc[mi][ni][1], 0.f));
            float d10 = sqrtf(fmaxf(si1 + sj0 - 2.f * acc[mi][ni][2], 0.f));
            float d11 = sqrtf(fmaxf(si1 + sj1 - 2.f * acc[mi][ni][3], 0.f));
            stage[r0 * 132 + c0] = d00;
            stage[r0 * 132 + c0 + 1] = d01;
            stage[(r0 + 8) * 132 + c0] = d10;
            stage[(r0 + 8) * 132 + c0 + 1] = d11;
        }
    }
    __syncthreads();

    // normal store (coalesced rows)
    {
        int r = t >> 1, cb = (t & 1) * 64;
        const float* srow = stage + r * 132 + cb;
        float* drow = DIST + (size_t)(bi + r) * NN + bj + cb;
#pragma unroll
        for (int k = 0; k < 64; k += 4)
            *(float4*)(drow + k) = *(const float4*)(srow + k);
    }
    // mirrored store for off-diagonal tiles
    if (!diag) {
        int r = t >> 1, cb = (t & 1) * 64;
        float* drow = DIST + (size_t)(bj + r) * NN + bi + cb;
#pragma unroll
        for (int k = 0; k < 64; k += 4) {
            float4 v = make_float4(stage[(cb + k + 0) * 132 + r],
                                   stage[(cb + k + 1) * 132 + r],
                                   stage[(cb + k + 2) * 132 + r],
                                   stage[(cb + k + 3) * 132 + r]);
            *(float4*)(drow + k) = v;
        }
    }
}

// ================= rowsolve =================================================
// probs = -dist; zn = gamma*(probs-mean)/(std+eps)+beta, diag -> -1e-6.
// entmax support: u_j > T, T root of sum max(u_j-T,0)^2 = 1, u = zn/2,
// T in [max-1, max]. a<0 so rowmax(u) comes from off-diag rowmin(dist).
__global__ void __launch_bounds__(256)
rowsolve(const float* __restrict__ DIST, const float* __restrict__ gamma_p,
         const float* __restrict__ beta_p, float* __restrict__ Sthr,
         float* __restrict__ DF) {
    __shared__ float sv[NN];
    __shared__ float cand[CAP];
    __shared__ float red[8];
    __shared__ int ccnt;
    const int r = blockIdx.x;
    const int t = threadIdx.x;
    const float4* drow4 = (const float4*)(DIST + (size_t)r * NN);

    float s = 0.f, dmn = 3.4e38f;
    for (int j4 = t; j4 < NN / 4; j4 += 256) {
        float4 d = drow4[j4];
        *(float4*)(&sv[4 * j4]) = d;
        s += d.x + d.y + d.z + d.w;
        int jb = 4 * j4;
        float m0 = (jb + 0 != r) ? d.x : 3.4e38f;
        float m1 = (jb + 1 != r) ? d.y : 3.4e38f;
        float m2 = (jb + 2 != r) ? d.z : 3.4e38f;
        float m3 = (jb + 3 != r) ? d.w : 3.4e38f;
        dmn = fminf(dmn, fminf(fminf(m0, m1), fminf(m2, m3)));
    }
    __syncthreads();
    float sumd = blockSum(s, red);
    dmn = blockMin(dmn, red);
    float mean = -sumd * (1.0f / NN);

    float v2 = 0.f;
    for (int j = t; j < NN; j += 256) {
        float e = (-sv[j]) - mean;
        v2 += e * e;
    }
    float var = blockSum(v2, red) * (1.0f / (NN - 1));
    float stdv = sqrtf(var);
    float gamma = gamma_p[0], beta = beta_p[0];
    float scale = gamma / (stdv + 1e-6f);
    float a = -scale;                    // zn = a*dist + b
    float b = beta - scale * mean;

    float mx = fmaxf(0.5f * fmaf(a, dmn, b), -5e-7f);
    float cthr = mx - 1.0f;

    if (t == 0) ccnt = 0;
    __syncthreads();
    for (int j = t; j < NN; j += 256) {
        float u = (j == r) ? -5e-7f : 0.5f * fmaf(a, sv[j], b);
        if (u >= cthr) {
            int p = atomicAdd(&ccnt, 1);
            if (p < CAP) cand[p] = u;
        }
    }
    __syncthreads();
    int cnt = ccnt;
    if (cnt > CAP) {
        for (int j = t; j < NN; j += 256)
            sv[j] = (j == r) ? -5e-7f : 0.5f * fmaf(a, sv[j], b);
        __syncthreads();
    }
    const float* arr = (cnt <= CAP) ? cand : sv;
    const int n = (cnt <= CAP) ? cnt : NN;

    float lo = mx - 1.f, hi = mx, T = lo;
    for (int it = 0; it < 24; it++) {
        float f = 0.f, g = 0.f;
        for (int j = t; j < n; j += 256) {
            float w = arr[j] - T;
            if (w > 0.f) { f += w * w; g += w; }
        }
        f = blockSum(f, red);
        g = blockSum(g, red);
        f -= 1.f;
        if (f > 0.f) lo = T; else hi = T;
        float Tn = T + f / (2.f * g);
        if (!(Tn > lo && Tn < hi)) Tn = 0.5f * (lo + hi);
        T = Tn;
    }
    T = 0.5f * (lo + hi);

    if (t == 0) {
        float tzn = 2.f * T;
        Sthr[r] = (tzn - b) / a;
        DF[r] = (-1e-6f > tzn) ? 1.f : 0.f;
    }
}

// ================= finalize =================================================
__global__ void __launch_bounds__(256)
finalize(const float* __restrict__ DIST, const float* __restrict__ Sthr,
         const float* __restrict__ DF, float* __restrict__ resOut,
         float* __restrict__ logp) {
    __shared__ float sS[NN];
    __shared__ float red[8];
    const int i = blockIdx.x;
    const int t = threadIdx.x;
    for (int j = t; j < NN; j += 256) sS[j] = Sthr[j];
    __syncthreads();
    const float si = sS[i];
    const float dfi = DF[i];
    const float4* drow = (const float4*)(DIST + (size_t)i * NN);
    float4* orow = (float4*)(resOut + (size_t)i * NN);
    float cnt = 0.f;
    const int dq = i >> 2, dr = i & 3;
    for (int j4 = t; j4 < NN / 4; j4 += 256) {
        float4 d = drow[j4];
        float4 o;
        o.x = (d.x < fmaxf(si, sS[4 * j4 + 0])) ? 1.f : 0.f;
        o.y = (d.y < fmaxf(si, sS[4 * j4 + 1])) ? 1.f : 0.f;
        o.z = (d.z < fmaxf(si, sS[4 * j4 + 2])) ? 1.f : 0.f;
        o.w = (d.w < fmaxf(si, sS[4 * j4 + 3])) ? 1.f : 0.f;
        if (j4 == dq) ((float*)&o)[dr] = dfi;
        orow[j4] = o;
        cnt += o.x + o.y + o.z + o.w;
    }
    cnt = blockSum(cnt, red);
    if (t == 0) logp[i] = cnt;
}

// ================= launch ====================================================
extern "C" void kernel_launch(void* const* d_in, const int* in_sizes, int n_in,
                              void* d_out, int out_size) {
    const float* x     = (const float*)d_in[0];
    const float* W     = (const float*)d_in[1];
    const float* gamma = (const float*)d_in[2];
    const float* beta  = (const float*)d_in[3];
    const int*   edges = (const int*)d_in[4];
    int nE = in_sizes[4] / 2;

    float* out    = (float*)d_out;
    float* Hout   = out;
    float* resOut = out + (size_t)NN * DD;
    float* logp   = resOut + (size_t)NN * NN;

    void *pH0, *pACC, *pWt, *pSQ, *pDIST, *pS, *pDF, *pHh, *pHl;
    cudaGetSymbolAddress(&pH0, g_H0);
    cudaGetSymbolAddress(&pACC, g_ACC);
    cudaGetSymbolAddress(&pWt, g_Wt);
    cudaGetSymbolAddress(&pSQ, g_SQ);
    cudaGetSymbolAddress(&pDIST, g_DIST);
    cudaGetSymbolAddress(&pS, g_S);
    cudaGetSymbolAddress(&pDF, g_DF);
    cudaGetSymbolAddress(&pHh, g_Hh);
    cudaGetSymbolAddress(&pHl, g_Hl);

    static int attr_done = 0;
    if (!attr_done) {
        cudaFuncSetAttribute(dist_mma,
                             cudaFuncAttributeMaxDynamicSharedMemorySize, DIST_SMEM);
        attr_done = 1;
    }

    transpose_w<<<256, 256>>>(W, (float*)pWt);

    dim3 g1(DD / 128, NN / 128);
    gemm_h0<<<g1, 256>>>(x, (const float*)pWt, (float*)pH0, DD, DD);

    cudaMemsetAsync(pACC, 0, (size_t)NN * DD * sizeof(float));

    int sgrid = (nE * 64 + 255) / 256;
    scatter_edges<<<sgrid, 256>>>((const float*)pH0, edges, nE, (float*)pACC);

    relu_split<<<NN, 256>>>((const float*)pH0, (const float*)pACC, Hout,
                            (float*)pSQ, (__half*)pHh, (__half*)pHl);

    int ntiles = (NN / 128) * (NN / 128 + 1) / 2;   // 2080
    dist_mma<<<ntiles, 256, DIST_SMEM>>>((const __half*)pHh, (const __half*)pHl,
                                         (const float*)pSQ, (float*)pDIST);

    rowsolve<<<NN, 256>>>((const float*)pDIST, gamma, beta, (float*)pS, (float*)pDF);

    finalize<<<NN, 256>>>((const float*)pDIST, (const float*)pS, (const float*)pDF,
                          resOut, logp);
}

// round 9
// speedup vs baseline: 1.1048x; 1.1048x over previous
#include <cuda_runtime.h>
#include <cuda_fp16.h>
#include <math.h>
#include <stdint.h>

#define NN 8192
#define DD 256
#define CAP 2048

// ================= scratch (device globals) =================================
__device__ float  g_H0[NN * DD];            // x @ W (pre-relu, pre-agg)
__device__ float  g_ACC[NN * DD];           // segment-sum accumulator
__device__ float  g_Wt[DD * DD];            // W transposed
__device__ __half g_Hh[NN * DD];            // fp16 hi part of h
__device__ __half g_Hl[NN * DD];            // fp16 lo part (h - hi)
__device__ float  g_SQ[NN];                 // row squared norms of h
__device__ float  g_DIST[(size_t)NN * NN];  // pairwise distances (256 MB)
__device__ float  g_S[NN];                  // per-row distance threshold
__device__ float  g_DF[NN];                 // diagonal membership flag

// ================= PTX helpers ==============================================
__device__ __forceinline__ uint32_t smem_u32(const void* p) {
    uint32_t a;
    asm("{ .reg .u64 t; cvta.to.shared.u64 t, %1; cvt.u32.u64 %0, t; }"
        : "=r"(a) : "l"(p));
    return a;
}
__device__ __forceinline__ void cpa16(uint32_t dst, const void* src) {
    asm volatile("cp.async.cg.shared.global [%0], [%1], 16;"
                 :: "r"(dst), "l"(src) : "memory");
}
#define CPA_COMMIT() asm volatile("cp.async.commit_group;" ::: "memory")
#define CPA_WAIT(n)  asm volatile("cp.async.wait_group %0;" :: "n"(n) : "memory")

#define LDSM4(r0, r1, r2, r3, addr)                                           \
    asm volatile("ldmatrix.sync.aligned.m8n8.x4.shared.b16 {%0,%1,%2,%3}, [%4];" \
                 : "=r"(r0), "=r"(r1), "=r"(r2), "=r"(r3) : "r"(addr))

// D += A(16x16 f16) * B(16x8 f16)^T, fp32 accum
#define MMA16816(c, a, b)                                                     \
    asm volatile("mma.sync.aligned.m16n8k16.row.col.f32.f16.f16.f32 "         \
                 "{%0,%1,%2,%3}, {%4,%5,%6,%7}, {%8,%9}, {%0,%1,%2,%3};"      \
                 : "+f"((c)[0]), "+f"((c)[1]), "+f"((c)[2]), "+f"((c)[3])     \
                 : "r"((a)[0]), "r"((a)[1]), "r"((a)[2]), "r"((a)[3]),        \
                   "r"((b)[0]), "r"((b)[1]))

// ================= reductions ===============================================
__device__ __forceinline__ float blockSum(float v, float* red) {
    int lane = threadIdx.x & 31, wid = threadIdx.x >> 5;
#pragma unroll
    for (int o = 16; o; o >>= 1) v += __shfl_xor_sync(0xffffffffu, v, o);
    if (lane == 0) red[wid] = v;
    __syncthreads();
    if (threadIdx.x < 32) {
        float x = (lane < 8) ? red[lane] : 0.f;
#pragma unroll
        for (int o = 4; o; o >>= 1) x += __shfl_xor_sync(0xffffffffu, x, o);
        if (lane == 0) red[0] = x;
    }
    __syncthreads();
    float r = red[0];
    __syncthreads();
    return r;
}
__device__ __forceinline__ float blockMin(float v, float* red) {
    int lane = threadIdx.x & 31, wid = threadIdx.x >> 5;
#pragma unroll
    for (int o = 16; o; o >>= 1) v = fminf(v, __shfl_xor_sync(0xffffffffu, v, o));
    if (lane == 0) red[wid] = v;
    __syncthreads();
    if (threadIdx.x < 32) {
        float x = (lane < 8) ? red[lane] : 3.4e38f;
#pragma unroll
        for (int o = 4; o; o >>= 1) x = fminf(x, __shfl_xor_sync(0xffffffffu, x, o));
        if (lane == 0) red[0] = x;
    }
    __syncthreads();
    float r = red[0];
    __syncthreads();
    return r;
}

// ================= small kernels ============================================
__global__ void transpose_w(const float* __restrict__ W, float* __restrict__ Wt) {
    int idx = blockIdx.x * 256 + threadIdx.x;
    int n = idx >> 8, k = idx & 255;
    Wt[idx] = W[k * DD + n];
}

__global__ void __launch_bounds__(256)
scatter_edges(const float* __restrict__ H0, const int* __restrict__ edges, int nE,
              float* __restrict__ ACC) {
    int gid = blockIdx.x * 256 + threadIdx.x;
    int e = gid >> 6;
    if (e >= nE) return;
    int c = (gid & 63) << 2;
    int sN = edges[e];
    int dN = edges[nE + e];
    const float4 v = *(const float4*)(H0 + (size_t)sN * DD + c);
    float* p = ACC + (size_t)dN * DD + c;
    asm volatile("red.global.add.v4.f32 [%0], {%1,%2,%3,%4};"
                 :: "l"(p), "f"(v.x), "f"(v.y), "f"(v.z), "f"(v.w) : "memory");
}

// h = relu(H0+ACC) -> Hout; SQ = |h|^2; fp16 split -> Hh, Hl
__global__ void __launch_bounds__(256)
relu_split(const float* __restrict__ H0, const float* __restrict__ ACC,
           float* __restrict__ Hout, float* __restrict__ SQ,
           __half* __restrict__ Hh, __half* __restrict__ Hl) {
    __shared__ float red[8];
    int r = blockIdx.x, c = threadIdx.x;
    size_t i = (size_t)r * DD + c;
    float v = fmaxf(H0[i] + ACC[i], 0.f);
    Hout[i] = v;
    __half hh = __float2half_rn(v);
    float lo = v - __half2float(hh);
    Hh[i] = hh;
    Hl[i] = __float2half_rn(lo);
    float ss = blockSum(v * v, red);
    if (c == 0) SQ[r] = ss;
}

// ================= SIMT NT SGEMM for H0 = x @ W (f32x2) =====================
__device__ __forceinline__ unsigned long long dup2(float x) {
    unsigned long long r;
    asm("mov.b64 %0, {%1,%1};" : "=l"(r) : "f"(x));
    return r;
}
__device__ __forceinline__ void ffma2(unsigned long long& d, unsigned long long a,
                                      unsigned long long b) {
    asm("fma.rn.f32x2 %0, %1, %2, %0;" : "+l"(d) : "l"(a), "l"(b));
}
__device__ __forceinline__ float2 unpack2(unsigned long long v) {
    float2 r;
    asm("mov.b64 {%0,%1}, %2;" : "=f"(r.x), "=f"(r.y) : "l"(v));
    return r;
}

__global__ void __launch_bounds__(256)
gemm_h0(const float* __restrict__ A, const float* __restrict__ B,
        float* __restrict__ C, int N, int K) {
    __shared__ float As[8][132];
    __shared__ float Bs[8][132];
    const int bi = blockIdx.y * 128;
    const int bj = blockIdx.x * 128;
    const int t = threadIdx.x;
    const int tx = t & 15, ty = t >> 4;
    const int lr = t >> 1, lc = (t & 1) * 4;

    unsigned long long acc2[8][4];
#pragma unroll
    for (int i = 0; i < 8; i++)
#pragma unroll
        for (int j = 0; j < 4; j++) acc2[i][j] = 0ull;

    const float* Ag = A + (size_t)(bi + lr) * K + lc;
    const float* Bg = B + (size_t)(bj + lr) * K + lc;
    float4 av = *(const float4*)Ag;
    float4 bv = *(const float4*)Bg;

    for (int k0 = 0; k0 < K; k0 += 8) {
        As[lc + 0][lr] = av.x; As[lc + 1][lr] = av.y;
        As[lc + 2][lr] = av.z; As[lc + 3][lr] = av.w;
        Bs[lc + 0][lr] = bv.x; Bs[lc + 1][lr] = bv.y;
        Bs[lc + 2][lr] = bv.z; Bs[lc + 3][lr] = bv.w;
        __syncthreads();
        if (k0 + 8 < K) {
            av = *(const float4*)(Ag + k0 + 8);
            bv = *(const float4*)(Bg + k0 + 8);
        }
#pragma unroll
        for (int kk = 0; kk < 8; kk++) {
            float ar[8];
            *(float4*)(ar)     = *(const float4*)(&As[kk][ty * 8]);
            *(float4*)(ar + 4) = *(const float4*)(&As[kk][ty * 8 + 4]);
            const unsigned long long* bp = (const unsigned long long*)(&Bs[kk][tx * 8]);
            unsigned long long b0 = bp[0], b1 = bp[1], b2 = bp[2], b3 = bp[3];
#pragma unroll
            for (int i = 0; i < 8; i++) {
                unsigned long long ai = dup2(ar[i]);
                ffma2(acc2[i][0], ai, b0);
                ffma2(acc2[i][1], ai, b1);
                ffma2(acc2[i][2], ai, b2);
                ffma2(acc2[i][3], ai, b3);
            }
        }
        __syncthreads();
    }
#pragma unroll
    for (int i = 0; i < 8; i++) {
        size_t row = (size_t)(bi + ty * 8 + i) * N + bj + tx * 8;
        float2 v0 = unpack2(acc2[i][0]), v1 = unpack2(acc2[i][1]);
        float2 v2 = unpack2(acc2[i][2]), v3 = unpack2(acc2[i][3]);
        *(float4*)(C + row)     = make_float4(v0.x, v0.y, v1.x, v1.y);
        *(float4*)(C + row + 4) = make_float4(v2.x, v2.y, v3.x, v3.y);
    }
}

// ================= fp16x3 mma.sync dist GEMM (triangular) ===================
// CTA tile 128x128, K=256 in 8 buffers of K=32, double-buffered cp.async.
// dot = Hh*Hh^T + Hh*Hl^T + Hl*Hh^T; epi: dist = sqrt(sq_i+sq_j-2dot),
// stored normal + mirrored (dist is symmetric).
//
// SMEM (bytes): [0,512) sq_i  [512,1024) sq_j  [1024,+) buffers / fp32 stage
// buffer b at 1024 + b*40960; slabs: Ahi +0, Alo +10240, Bhi +20480, Blo +30720
// each slab: 128 rows x 32 halfs, row stride 80B (64 data + 16 pad:
// r*80 mod 128 covers all eight 16B groups -> ldmatrix conflict-free).
#define ROW_STRIDE 80
#define SLAB_BYTES 10240
#define BUF_BYTES 40960
#define DIST_SMEM (1024 + 2 * BUF_BYTES)   // 82944 (stage 128*132*4=67584 aliases)

static __device__ __forceinline__ void load_chunk32(
    int t, uint32_t bufBase, int c, int bi, int bj,
    const __half* __restrict__ Hh, const __half* __restrict__ Hl) {
#pragma unroll
    for (int it = 0; it < 2; it++) {
        int idx = t + it * 256;            // 0..511
        int row = idx >> 2, seg = idx & 3;
        uint32_t d = bufBase + (uint32_t)(row * ROW_STRIDE + seg * 16);
        size_t ko = (size_t)c * 32 + seg * 8;
        cpa16(d,                  Hh + (size_t)(bi + row) * DD + ko);
        cpa16(d + SLAB_BYTES,     Hl + (size_t)(bi + row) * DD + ko);
        cpa16(d + 2 * SLAB_BYTES, Hh + (size_t)(bj + row) * DD + ko);
        cpa16(d + 3 * SLAB_BYTES, Hl + (size_t)(bj + row) * DD + ko);
    }
}

__global__ void __launch_bounds__(256, 2)
dist_mma(const __half* __restrict__ Hh, const __half* __restrict__ Hl,
         const float* __restrict__ SQ, float* __restrict__ DIST) {
    extern __shared__ char dyn[];
    const uint32_t sb = smem_u32(dyn);
    const int t = threadIdx.x;
    const int w = t >> 5, lane = t & 31;

    // triangular tile mapping: blockIdx.x -> (i, j), j <= i
    int L = blockIdx.x;
    int i = (int)((sqrtf(8.f * (float)L + 1.f) - 1.f) * 0.5f);
    while ((i + 1) * (i + 2) / 2 <= L) i++;
    while (i * (i + 1) / 2 > L) i--;
    int j = L - i * (i + 1) / 2;
    const int bi = i * 128;
    const int bj = j * 128;
    const bool diag = (bi == bj);

    if (t < 128) ((float*)dyn)[t] = SQ[bi + t];
    else         ((float*)dyn)[t] = SQ[bj + t - 128];

    const int mOff = (w >> 2) * 64;     // 2 warp-rows of 64
    const int nOff = (w & 3) * 32;      // 4 warp-cols of 32

    float acc[4][4][4];
#pragma unroll
    for (int a = 0; a < 4; a++)
#pragma unroll
        for (int b = 0; b < 4; b++)
#pragma unroll
            for (int c = 0; c < 4; c++) acc[a][b][c] = 0.f;

    load_chunk32(t, sb + 1024, 0, bi, bj, Hh, Hl);
    CPA_COMMIT();

    // per-lane ldmatrix offsets (within a buffer)
    const uint32_t aOff = (uint32_t)((mOff + (lane & 15)) * ROW_STRIDE
                                     + (lane >> 4) * 16);
    const uint32_t bOff = (uint32_t)(2 * SLAB_BYTES +
        (nOff + ((lane >> 4) * 8) + (lane & 7)) * ROW_STRIDE
        + ((lane >> 3) & 1) * 16);

    for (int s = 0; s < 8; s++) {
        uint32_t buf = sb + 1024 + (uint32_t)(s & 1) * BUF_BYTES;
        if (s < 7) {
            load_chunk32(t, sb + 1024 + (uint32_t)((s + 1) & 1) * BUF_BYTES,
                         s + 1, bi, bj, Hh, Hl);
            CPA_COMMIT();
            CPA_WAIT(1);
        } else {
            CPA_WAIT(0);
        }
        __syncthreads();

#pragma unroll
        for (int k16 = 0; k16 < 2; k16++) {
            uint32_t ka = buf + aOff + k16 * 32;
            uint32_t kb = buf + bOff + k16 * 32;
            uint32_t ahi[4][4], alo[4][4], bhi[4][2], blo[4][2];
#pragma unroll
            for (int mi = 0; mi < 4; mi++) {
                uint32_t ad = ka + mi * 16 * ROW_STRIDE;
                LDSM4(ahi[mi][0], ahi[mi][1], ahi[mi][2], ahi[mi][3], ad);
                LDSM4(alo[mi][0], alo[mi][1], alo[mi][2], alo[mi][3],
                      ad + SLAB_BYTES);
            }
#pragma unroll
            for (int p = 0; p < 2; p++) {
                uint32_t bd = kb + p * 16 * ROW_STRIDE;
                uint32_t r0, r1, r2, r3;
                LDSM4(r0, r1, r2, r3, bd);
                bhi[2 * p][0] = r0; bhi[2 * p][1] = r1;
                bhi[2 * p + 1][0] = r2; bhi[2 * p + 1][1] = r3;
                LDSM4(r0, r1, r2, r3, bd + SLAB_BYTES);
                blo[2 * p][0] = r0; blo[2 * p][1] = r1;
                blo[2 * p + 1][0] = r2; blo[2 * p + 1][1] = r3;
            }
#pragma unroll
            for (int mi = 0; mi < 4; mi++)
#pragma unroll
                for (int ni = 0; ni < 4; ni++) {
                    MMA16816(acc[mi][ni], ahi[mi], bhi[ni]);
                    MMA16816(acc[mi][ni], ahi[mi], blo[ni]);
                    MMA16816(acc[mi][ni], alo[mi], bhi[ni]);
                }
        }
        __syncthreads();
    }

    // ---- epilogue: dist = sqrt(max(sq_i + sq_j - 2*dot, 0)) ----------------
    const float* sqi = (const float*)dyn;
    const float* sqj = (const float*)dyn + 128;
    float* stage = (float*)(dyn + 1024);        // [128][132]
    const int g = lane >> 2, tc2 = (lane & 3) * 2;

#pragma unroll
    for (int mi = 0; mi < 4; mi++) {
        int r0 = mOff + mi * 16 + g;
        float si0 = sqi[r0], si1 = sqi[r0 + 8];
#pragma unroll
        for (int ni = 0; ni < 4; ni++) {
            int c0 = nOff + ni * 8 + tc2;
            float sj0 = sqj[c0], sj1 = sqj[c0 + 1];
            float d00 = sqrtf(fmaxf(si0 + sj0 - 2.f * acc[mi][ni][0], 0.f));
            float d01 = sqrtf(fmaxf(si0 + sj1 - 2.f * acc[mi][ni][1], 0.f));
            float d10 = sqrtf(fmaxf(si1 + sj0 - 2.f * acc[mi][ni][2], 0.f));
            float d11 = sqrtf(fmaxf(si1 + sj1 - 2.f * acc[mi][ni][3], 0.f));
            stage[r0 * 132 + c0] = d00;
            stage[r0 * 132 + c0 + 1] = d01;
            stage[(r0 + 8) * 132 + c0] = d10;
            stage[(r0 + 8) * 132 + c0 + 1] = d11;
        }
    }
    __syncthreads();

    {
        int r = t >> 1, cb = (t & 1) * 64;
        const float* srow = stage + r * 132 + cb;
        float* drow = DIST + (size_t)(bi + r) * NN + bj + cb;
#pragma unroll
        for (int k = 0; k < 64; k += 4)
            *(float4*)(drow + k) = *(const float4*)(srow + k);
    }
    if (!diag) {
        int r = t >> 1, cb = (t & 1) * 64;
        float* drow = DIST + (size_t)(bj + r) * NN + bi + cb;
#pragma unroll
        for (int k = 0; k < 64; k += 4) {
            float4 v = make_float4(stage[(cb + k + 0) * 132 + r],
                                   stage[(cb + k + 1) * 132 + r],
                                   stage[(cb + k + 2) * 132 + r],
                                   stage[(cb + k + 3) * 132 + r]);
            *(float4*)(drow + k) = v;
        }
    }
}

// ================= rowsolve =================================================
// probs = -dist; zn = gamma*(probs-mean)/(std+eps)+beta, diag -> -1e-6.
// entmax support: u_j > T, T root of sum max(u_j-T,0)^2 = 1, u = zn/2,
// T in [max-1, max]. a<0 so rowmax(u) comes from off-diag rowmin(dist).
__global__ void __launch_bounds__(256)
rowsolve(const float* __restrict__ DIST, const float* __restrict__ gamma_p,
         const float* __restrict__ beta_p, float* __restrict__ Sthr,
         float* __restrict__ DF) {
    __shared__ float sv[NN];
    __shared__ float cand[CAP];
    __shared__ float red[8];
    __shared__ int ccnt;
    const int r = blockIdx.x;
    const int t = threadIdx.x;
    const float4* drow4 = (const float4*)(DIST + (size_t)r * NN);

    float s = 0.f, dmn = 3.4e38f;
    for (int j4 = t; j4 < NN / 4; j4 += 256) {
        float4 d = drow4[j4];
        *(float4*)(&sv[4 * j4]) = d;
        s += d.x + d.y + d.z + d.w;
        int jb = 4 * j4;
        float m0 = (jb + 0 != r) ? d.x : 3.4e38f;
        float m1 = (jb + 1 != r) ? d.y : 3.4e38f;
        float m2 = (jb + 2 != r) ? d.z : 3.4e38f;
        float m3 = (jb + 3 != r) ? d.w : 3.4e38f;
        dmn = fminf(dmn, fminf(fminf(m0, m1), fminf(m2, m3)));
    }
    __syncthreads();
    float sumd = blockSum(s, red);
    dmn = blockMin(dmn, red);
    float mean = -sumd * (1.0f / NN);

    float v2 = 0.f;
    for (int j = t; j < NN; j += 256) {
        float e = (-sv[j]) - mean;
        v2 += e * e;
    }
    float var = blockSum(v2, red) * (1.0f / (NN - 1));
    float stdv = sqrtf(var);
    float gamma = gamma_p[0], beta = beta_p[0];
    float scale = gamma / (stdv + 1e-6f);
    float a = -scale;                    // zn = a*dist + b
    float b = beta - scale * mean;

    float mx = fmaxf(0.5f * fmaf(a, dmn, b), -5e-7f);
    float cthr = mx - 1.0f;

    if (t == 0) ccnt = 0;
    __syncthreads();
    for (int j = t; j < NN; j += 256) {
        float u = (j == r) ? -5e-7f : 0.5f * fmaf(a, sv[j], b);
        if (u >= cthr) {
            int p = atomicAdd(&ccnt, 1);
            if (p < CAP) cand[p] = u;
        }
    }
    __syncthreads();
    int cnt = ccnt;
    if (cnt > CAP) {
        for (int j = t; j < NN; j += 256)
            sv[j] = (j == r) ? -5e-7f : 0.5f * fmaf(a, sv[j], b);
        __syncthreads();
    }
    const float* arr = (cnt <= CAP) ? cand : sv;
    const int n = (cnt <= CAP) ? cnt : NN;

    float lo = mx - 1.f, hi = mx, T = lo;
    for (int it = 0; it < 24; it++) {
        float f = 0.f, g = 0.f;
        for (int j = t; j < n; j += 256) {
            float w = arr[j] - T;
            if (w > 0.f) { f += w * w; g += w; }
        }
        f = blockSum(f, red);
        g = blockSum(g, red);
        f -= 1.f;
        if (f > 0.f) lo = T; else hi = T;
        float Tn = T + f / (2.f * g);
        if (!(Tn > lo && Tn < hi)) Tn = 0.5f * (lo + hi);
        T = Tn;
    }
    T = 0.5f * (lo + hi);

    if (t == 0) {
        float tzn = 2.f * T;
        Sthr[r] = (tzn - b) / a;
        DF[r] = (-1e-6f > tzn) ? 1.f : 0.f;
    }
}

// ================= finalize (4 rows per block) ==============================
__global__ void __launch_bounds__(256)
finalize(const float* __restrict__ DIST, const float* __restrict__ Sthr,
         const float* __restrict__ DF, float* __restrict__ resOut,
         float* __restrict__ logp) {
    __shared__ float sS[NN];
    __shared__ float red[8];
    const int t = threadIdx.x;
    for (int j = t; j < NN; j += 256) sS[j] = Sthr[j];
    __syncthreads();

#pragma unroll
    for (int rr = 0; rr < 4; rr++) {
        const int i = blockIdx.x * 4 + rr;
        const float si = sS[i];
        const float dfi = DF[i];
        const float4* drow = (const float4*)(DIST + (size_t)i * NN);
        float4* orow = (float4*)(resOut + (size_t)i * NN);
        float cnt = 0.f;
        const int dq = i >> 2, dr = i & 3;
        for (int j4 = t; j4 < NN / 4; j4 += 256) {
            float4 d = drow[j4];
            float4 o;
            o.x = (d.x < fmaxf(si, sS[4 * j4 + 0])) ? 1.f : 0.f;
            o.y = (d.y < fmaxf(si, sS[4 * j4 + 1])) ? 1.f : 0.f;
            o.z = (d.z < fmaxf(si, sS[4 * j4 + 2])) ? 1.f : 0.f;
            o.w = (d.w < fmaxf(si, sS[4 * j4 + 3])) ? 1.f : 0.f;
            if (j4 == dq) ((float*)&o)[dr] = dfi;
            orow[j4] = o;
            cnt += o.x + o.y + o.z + o.w;
        }
        cnt = blockSum(cnt, red);
        if (t == 0) logp[i] = cnt;
        __syncthreads();
    }
}

// ================= launch ====================================================
extern "C" void kernel_launch(void* const* d_in, const int* in_sizes, int n_in,
                              void* d_out, int out_size) {
    const float* x     = (const float*)d_in[0];
    const float* W     = (const float*)d_in[1];
    const float* gamma = (const float*)d_in[2];
    const float* beta  = (const float*)d_in[3];
    const int*   edges = (const int*)d_in[4];
    int nE = in_sizes[4] / 2;

    float* out    = (float*)d_out;
    float* Hout   = out;
    float* resOut = out + (size_t)NN * DD;
    float* logp   = resOut + (size_t)NN * NN;

    void *pH0, *pACC, *pWt, *pSQ, *pDIST, *pS, *pDF, *pHh, *pHl;
    cudaGetSymbolAddress(&pH0, g_H0);
    cudaGetSymbolAddress(&pACC, g_ACC);
    cudaGetSymbolAddress(&pWt, g_Wt);
    cudaGetSymbolAddress(&pSQ, g_SQ);
    cudaGetSymbolAddress(&pDIST, g_DIST);
    cudaGetSymbolAddress(&pS, g_S);
    cudaGetSymbolAddress(&pDF, g_DF);
    cudaGetSymbolAddress(&pHh, g_Hh);
    cudaGetSymbolAddress(&pHl, g_Hl);

    static int attr_done = 0;
    if (!attr_done) {
        cudaFuncSetAttribute(dist_mma,
                             cudaFuncAttributeMaxDynamicSharedMemorySize, DIST_SMEM);
        attr_done = 1;
    }

    transpose_w<<<256, 256>>>(W, (float*)pWt);

    dim3 g1(DD / 128, NN / 128);
    gemm_h0<<<g1, 256>>>(x, (const float*)pWt, (float*)pH0, DD, DD);

    cudaMemsetAsync(pACC, 0, (size_t)NN * DD * sizeof(float));

    int sgrid = (nE * 64 + 255) / 256;
    scatter_edges<<<sgrid, 256>>>((const float*)pH0, edges, nE, (float*)pACC);

    relu_split<<<NN, 256>>>((const float*)pH0, (const float*)pACC, Hout,
                            (float*)pSQ, (__half*)pHh, (__half*)pHl);

    int ntiles = (NN / 128) * (NN / 128 + 1) / 2;   // 2080
    dist_mma<<<ntiles, 256, DIST_SMEM>>>((const __half*)pHh, (const __half*)pHl,
                                         (const float*)pSQ, (float*)pDIST);

    rowsolve<<<NN, 256>>>((const float*)pDIST, gamma, beta, (float*)pS, (float*)pDF);

    finalize<<<NN / 4, 256>>>((const float*)pDIST, (const float*)pS, (const float*)pDF,
                              resOut, logp);
}